// round 12
// baseline (speedup 1.0000x reference)
#include <cuda_runtime.h>
#include <cstddef>
#include <cstdint>

// MoEGate, 2-phase: (A) W transpose+permute -> wT[k][perm(e)],
// (B) fused GEMM+epilogue: in-block split-K (two 32-chunk half passes into
// separate register sums, added at the end — bit-identical to the R10
// split-K-across-blocks numerics), then softmax/top-6/renorm/aux in the
// same kernel. No logits roundtrip, no epilogue launch, single GEMM wave.
// x: [T=16384, h=2048] f32, W: [E=64, h] f32.
// Output (f32): [topk_idx (T*6) | topk_weight (T*6) | aux_loss (1)]

#define NE 64
#define KTOP 6
#define NB 4
#define MAXH 2048
#define TPB 64                // tokens per block
#define THREADS 128           // 4 warps; lane = lt*8 + le
#define CHUNK 32              // k per stage
#define XPITCH 36             // floats per staged x row
#define NBLK 256              // T / TPB
#define BPB 64                // blocks per batch = NBLK / NB

__device__ float    g_wt[MAXH * NE];             // wT[k][perm(e)], 512KB
__device__ float    g_pscore[NBLK * NE];
__device__ int      g_pcnt[NBLK * NE];
__device__ unsigned g_ticket;                    // self-resetting

static __device__ __forceinline__ void ffma2(unsigned long long& d,
                                             unsigned long long a,
                                             unsigned long long b) {
    asm("fma.rn.f32x2 %0, %1, %2, %0;" : "+l"(d) : "l"(a), "l"(b));
}
static __device__ __forceinline__ void add2(unsigned long long& d,
                                            unsigned long long a) {
    asm("add.rn.f32x2 %0, %0, %1;" : "+l"(d) : "l"(a));
}
static __device__ __forceinline__ unsigned long long dup2(float f) {
    unsigned long long r;
    asm("mov.b64 %0, {%1, %1};" : "=l"(r) : "f"(f));
    return r;
}
static __device__ __forceinline__ void cpa16(uint32_t dst, const void* src) {
    asm volatile("cp.async.cg.shared.global [%0], [%1], 16;"
                 :: "r"(dst), "l"(src));
}

// ---------------- A: transpose W[e][k] -> wT[k][perm(e)] ----------------
// perm(e): e = 8*le + i  ->  (i&4)*8 + le*4 + (i&3)
__global__ void transpose_kernel(const float* __restrict__ w, int h) {
    __shared__ float s[16 * 65];
    const int k0 = blockIdx.x * 16;
    for (int idx = threadIdx.x; idx < 16 * 64; idx += 256) {
        int e = idx >> 4, kk = idx & 15;
        s[kk * 65 + e] = w[(size_t)e * h + k0 + kk];
    }
    __syncthreads();
    for (int idx = threadIdx.x; idx < 16 * 64; idx += 256) {
        int kk = idx >> 6, e = idx & 63;
        int le = e >> 3, i = e & 7;
        int pos = ((i & 4) << 3) + le * 4 + (i & 3);
        g_wt[(size_t)(k0 + kk) * NE + pos] = s[kk * 65 + e];
    }
}

// ---------------- B: fused GEMM + epilogue ----------------
__global__ __launch_bounds__(THREADS) void moe_kernel(
    const float* __restrict__ x, float* __restrict__ out,
    int h, int T, int S)
{
    __shared__ __align__(16) float xs[2][TPB * XPITCH];   // 18KB
    __shared__ __align__(16) float wts[2][CHUNK * NE];    // 16KB
    __shared__ float score_acc[NE];
    __shared__ int   cnt_acc[NE];
    __shared__ unsigned is_last;
    __shared__ float part[4];

    const int tid  = threadIdx.x;
    const int lane = tid & 31;
    const int warp = tid >> 5;
    const int lt   = lane >> 3;       // token group 0..3
    const int le   = lane & 7;        // expert group 0..7
    const int bid  = blockIdx.x;
    const int tok0 = bid * TPB;
    const int nchunk = h / CHUNK;          // 64
    const int halfc  = nchunk >> 1;        // 32

    if (tid < NE) { score_acc[tid] = 0.0f; cnt_acc[tid] = 0; }

    unsigned long long acc[4][4], sumA[4][4], sumB[4][4];
#pragma unroll
    for (int j = 0; j < 4; j++)
#pragma unroll
        for (int p = 0; p < 4; p++) {
            acc[j][p] = 0ull; sumA[j][p] = 0ull; sumB[j][p] = 0ull;
        }

    // stage: x 64 rows x 8 quads (512) + wT 32 rows x 16 quads (512)
    auto stage = [&](int c, int buf) {
        const int k0 = c * CHUNK;
#pragma unroll
        for (int j = 0; j < 8; j++) {
            int cj = tid + j * THREADS;
            if (cj < 512) {
                int row = cj >> 3, q = cj & 7;
                cpa16((uint32_t)__cvta_generic_to_shared(
                          &xs[buf][row * XPITCH + q * 4]),
                      x + (size_t)(tok0 + row) * h + k0 + q * 4);
            } else {
                int c2 = cj - 512;
                int k = c2 >> 4, q = c2 & 15;
                cpa16((uint32_t)__cvta_generic_to_shared(
                          &wts[buf][k * NE + q * 4]),
                      g_wt + (size_t)(k0 + k) * NE + q * 4);
            }
        }
    };

    stage(0, 0);
    asm volatile("cp.async.commit_group;" ::: "memory");

    for (int c = 0; c < nchunk; c++) {
        const int buf = c & 1;
        asm volatile("cp.async.wait_group 0;" ::: "memory");
        __syncthreads();
        if (c + 1 < nchunk) {
            stage(c + 1, buf ^ 1);
            asm volatile("cp.async.commit_group;" ::: "memory");
        }

        const float* xb = &xs[buf][(warp * 16 + lt * 4) * XPITCH];
        const float* wb = &wts[buf][le * 4];   // wlo at +0, whi at +32
#pragma unroll
        for (int kk = 0; kk < CHUNK; kk += 4) {
            float4 xv0 = *(const float4*)(xb + 0 * XPITCH + kk);
            float4 xv1 = *(const float4*)(xb + 1 * XPITCH + kk);
            float4 xv2 = *(const float4*)(xb + 2 * XPITCH + kk);
            float4 xv3 = *(const float4*)(xb + 3 * XPITCH + kk);
#pragma unroll
            for (int k2 = 0; k2 < 4; k2++) {
                ulonglong2 wlo = *(const ulonglong2*)(wb + (kk + k2) * NE);
                ulonglong2 whi = *(const ulonglong2*)(wb + (kk + k2) * NE + 32);
                unsigned long long d0 = dup2(((const float*)&xv0)[k2]);
                unsigned long long d1 = dup2(((const float*)&xv1)[k2]);
                unsigned long long d2 = dup2(((const float*)&xv2)[k2]);
                unsigned long long d3 = dup2(((const float*)&xv3)[k2]);
                ffma2(acc[0][0], d0, wlo.x); ffma2(acc[0][1], d0, wlo.y);
                ffma2(acc[0][2], d0, whi.x); ffma2(acc[0][3], d0, whi.y);
                ffma2(acc[1][0], d1, wlo.x); ffma2(acc[1][1], d1, wlo.y);
                ffma2(acc[1][2], d1, whi.x); ffma2(acc[1][3], d1, whi.y);
                ffma2(acc[2][0], d2, wlo.x); ffma2(acc[2][1], d2, wlo.y);
                ffma2(acc[2][2], d2, whi.x); ffma2(acc[2][3], d2, whi.y);
                ffma2(acc[3][0], d3, wlo.x); ffma2(acc[3][1], d3, wlo.y);
                ffma2(acc[3][2], d3, whi.x); ffma2(acc[3][3], d3, whi.y);
            }
        }
        // merge chunk partials into the half's running sum (same bits as
        // the split-K-across-blocks version)
        if (c < halfc) {
#pragma unroll
            for (int j = 0; j < 4; j++)
#pragma unroll
                for (int p = 0; p < 4; p++) { add2(sumA[j][p], acc[j][p]); acc[j][p] = 0ull; }
        } else {
#pragma unroll
            for (int j = 0; j < 4; j++)
#pragma unroll
                for (int p = 0; p < 4; p++) { add2(sumB[j][p], acc[j][p]); acc[j][p] = 0ull; }
        }
    }
    __syncthreads();   // score_acc/cnt_acc init visible (also smem reuse safe)

    // ---- in-kernel epilogue: lane owns tokens warp*16+lt*4+{0..3},
    // experts 8le..8le+7 (pairs p -> v[2p], v[2p+1])
    for (int j = 0; j < 4; j++) {
        const int t = tok0 + warp * 16 + lt * 4 + j;
        float v[8];
#pragma unroll
        for (int p = 0; p < 4; p++) {
            union { unsigned long long u; float2 f; } ca, cb;
            ca.u = sumA[j][p]; cb.u = sumB[j][p];
            v[2 * p]     = ca.f.x + cb.f.x;   // same add as old epi kernel
            v[2 * p + 1] = ca.f.y + cb.f.y;
        }

        float m = v[0];
#pragma unroll
        for (int i = 1; i < 8; i++) m = fmaxf(m, v[i]);
#pragma unroll
        for (int off = 1; off < 8; off <<= 1)
            m = fmaxf(m, __shfl_xor_sync(0xffffffffu, m, off));

        float s[8], z = 0.0f;
#pragma unroll
        for (int i = 0; i < 8; i++) { s[i] = __expf(v[i] - m); z += s[i]; }
#pragma unroll
        for (int off = 1; off < 8; off <<= 1)
            z += __shfl_xor_sync(0xffffffffu, z, off);
        float inv = 1.0f / z;
#pragma unroll
        for (int i = 0; i < 8; i++) {
            s[i] *= inv;
            atomicAdd(&score_acc[8 * le + i], s[i]);
        }

        unsigned used = 0;
        float wsum = 0.0f;
        float outw[KTOP]; int outi[KTOP];
#pragma unroll
        for (int it = 0; it < KTOP; it++) {
            float bv = -3.4e38f; int bi = 127;
#pragma unroll
            for (int i = 0; i < 8; i++) {
                bool ok = !((used >> i) & 1u) && (v[i] > bv);
                bv = ok ? v[i] : bv;
                bi = ok ? (8 * le + i) : bi;
            }
#pragma unroll
            for (int off = 1; off < 8; off <<= 1) {
                float ov = __shfl_xor_sync(0xffffffffu, bv, off);
                int   oi = __shfl_xor_sync(0xffffffffu, bi, off);
                if (ov > bv || (ov == bv && oi < bi)) { bv = ov; bi = oi; }
            }
            int ii = bi & 7;
            float cand = s[0];
#pragma unroll
            for (int i = 1; i < 8; i++) cand = (ii == i) ? s[i] : cand;
            float sc = __shfl_sync(0xffffffffu, cand, (lane & 24) | (bi >> 3));
            wsum += sc;
            outw[it] = sc; outi[it] = bi;
            if ((bi >> 3) == le) used |= 1u << (bi & 7);
            if (le == 0) atomicAdd(&cnt_acc[bi], 1);
        }
        if (le == 0) {
            float invw = 1.0f / (wsum + 1e-20f);
#pragma unroll
            for (int it = 0; it < KTOP; it++) {
                out[(size_t)t * KTOP + it] = (float)outi[it];
                out[(size_t)T * KTOP + (size_t)t * KTOP + it] = outw[it] * invw;
            }
        }
    }
    __syncthreads();

    // ---- per-block partials + last-block aux reduction
    if (tid < NE) {
        g_pscore[bid * NE + tid] = score_acc[tid];
        g_pcnt[bid * NE + tid]   = cnt_acc[tid];
    }
    __threadfence();
    __syncthreads();
    if (tid == 0) {
        unsigned tkt = atomicAdd(&g_ticket, 1u);
        is_last = (tkt == (unsigned)(gridDim.x - 1));
    }
    __syncthreads();

    if (is_last) {
        if (tid == 0) g_ticket = 0;
        __threadfence();
        float local = 0.0f;
        for (int p = tid; p < NB * NE; p += THREADS) {
            int b = p >> 6, e = p & 63;
            float sc = 0.0f; int cn = 0;
            const int base = b * BPB;
            for (int blk = 0; blk < BPB; blk++) {
                sc += g_pscore[(base + blk) * NE + e];
                cn += g_pcnt[(base + blk) * NE + e];
            }
            float ce = (float)cn * ((float)NE / ((float)S * (float)KTOP));
            local += ce * (sc / (float)S);
        }
#pragma unroll
        for (int off = 16; off; off >>= 1)
            local += __shfl_xor_sync(0xffffffffu, local, off);
        if (lane == 0) part[warp] = local;
        __syncthreads();
        if (tid == 0) {
            float sm = part[0] + part[1] + part[2] + part[3];
            out[(size_t)2 * T * KTOP] = (sm / (float)NB) * 1e-3f;
        }
    }
}

extern "C" void kernel_launch(void* const* d_in, const int* in_sizes, int n_in,
                              void* d_out, int out_size) {
    const float* x = (const float*)d_in[0];
    const float* w = (const float*)d_in[1];
    float* out = (float*)d_out;
    int h = in_sizes[1] / NE;     // 2048
    int T = in_sizes[0] / h;      // 16384
    int S = T / NB;               // 4096

    transpose_kernel<<<h / 16, 256>>>(w, h);
    moe_kernel<<<T / TPB, THREADS>>>(x, out, h, T, S);
}

// round 13
// speedup vs baseline: 1.0977x; 1.0977x over previous
#include <cuda_runtime.h>
#include <cstddef>
#include <cstdint>

// MoEGate, 3-phase: (A) W transpose+permute, (B) split-K GEMM (mt=8,
// interleaved x rows, smem-resident chunk sums), (C) epilogue.
// x: [T=16384, h=2048] f32, W: [E=64, h] f32.
// Output (f32): [topk_idx (T*6) | topk_weight (T*6) | aux_loss (1)]
//
// R13: warp tile 32 tok x 64 exp (mt=8/lane). x staged with token rows
// interleaved (smem row = j*4+lt) so the 4 distinct addresses of each
// x-LDS.128 land on distinct banks (1 wavefront, was 4-way conflict).
// w perm keeps both w-LDS.128 single-wavefront. 16 wf per 128 FFMA2
// -> FMA-bound (~60us wall). Chunk sums live in smem (32KB) so regs
// hold only acc (128) - avoids R8's acc+sum=256 spill.
// Summation order per (t,e) bit-identical to R10/R12 (rel_err must
// stay exactly 2.876072e-7).

#define NE 64
#define KTOP 6
#define NB 4
#define MAXT 16384
#define MAXH 2048
#define TPB 128               // tokens per GEMM block (4 warps x 32)
#define THREADS 128           // lane = lt*8 + le
#define CHUNK 32              // k per stage
#define XPITCH 36             // floats per staged x row
#define EPB 64                // epilogue tokens per block
#define NBLK_C 256            // epilogue blocks = T/EPB
#define BPB 64                // epilogue blocks per batch

__device__ float    g_wt[MAXH * NE];             // wT[k][perm(e)], 512KB
__device__ float    g_logits[2][MAXT * NE];      // split-K partials, 8MB
__device__ float    g_pscore[NBLK_C * NE];
__device__ int      g_pcnt[NBLK_C * NE];
__device__ unsigned g_ticket;                    // self-resetting

static __device__ __forceinline__ void ffma2(unsigned long long& d,
                                             unsigned long long a,
                                             unsigned long long b) {
    asm("fma.rn.f32x2 %0, %1, %2, %0;" : "+l"(d) : "l"(a), "l"(b));
}
static __device__ __forceinline__ void add2(unsigned long long& d,
                                            unsigned long long a) {
    asm("add.rn.f32x2 %0, %0, %1;" : "+l"(d) : "l"(a));
}
static __device__ __forceinline__ unsigned long long dup2(float f) {
    unsigned long long r;
    asm("mov.b64 %0, {%1, %1};" : "=l"(r) : "f"(f));
    return r;
}
static __device__ __forceinline__ void cpa16(uint32_t dst, const void* src) {
    asm volatile("cp.async.cg.shared.global [%0], [%1], 16;"
                 :: "r"(dst), "l"(src));
}

// ---------------- A: transpose W[e][k] -> wT[k][perm(e)] ----------------
// perm(e): e = 8*le + i  ->  (i&4)*8 + le*4 + (i&3)
__global__ void transpose_kernel(const float* __restrict__ w, int h) {
    __shared__ float s[16 * 65];
    const int k0 = blockIdx.x * 16;
    for (int idx = threadIdx.x; idx < 16 * 64; idx += 256) {
        int e = idx >> 4, kk = idx & 15;
        s[kk * 65 + e] = w[(size_t)e * h + k0 + kk];
    }
    __syncthreads();
    for (int idx = threadIdx.x; idx < 16 * 64; idx += 256) {
        int kk = idx >> 6, e = idx & 63;
        int le = e >> 3, i = e & 7;
        int pos = ((i & 4) << 3) + le * 4 + (i & 3);
        g_wt[(size_t)(k0 + kk) * NE + pos] = s[kk * 65 + e];
    }
}

// ---------------- B: split-K GEMM -> partial logits ----------------
__global__ __launch_bounds__(THREADS) void gemm_kernel(
    const float* __restrict__ x, int h)
{
    __shared__ __align__(16) float xs[2][TPB * XPITCH];     // 36.9KB
    __shared__ __align__(16) float wts[2][CHUNK * NE];      // 16KB
    __shared__ ulonglong2 sum_s[8][2][THREADS];             // 32KB

    const int tid  = threadIdx.x;
    const int lane = tid & 31;
    const int warp = tid >> 5;
    const int lt   = lane >> 3;       // token subgroup 0..3
    const int le   = lane & 7;        // expert group 0..7
    const int tile = blockIdx.x >> 1;
    const int kh   = blockIdx.x & 1;  // k-half
    const int tok0 = tile * TPB;
    const int kbase = kh * (h >> 1);
    const int nchunk = (h >> 1) / CHUNK;   // 32

    // zero this thread's smem sums (own slots only -> no barrier needed)
#pragma unroll
    for (int j = 0; j < 8; j++)
#pragma unroll
        for (int pp = 0; pp < 2; pp++)
            sum_s[j][pp][tid] = make_ulonglong2(0ull, 0ull);

    unsigned long long acc[8][4];
#pragma unroll
    for (int j = 0; j < 8; j++)
#pragma unroll
        for (int p = 0; p < 4; p++) acc[j][p] = 0ull;

    // stage: x 128 rows x 8 quads (1024) + wT 32 rows x 16 quads (512).
    // x smem row r encodes token: r = wp*32 + j*4 + lt  (INTERLEAVED)
    //   -> global token = tok0 + wp*32 + lt*8 + j
    auto stage = [&](int c, int buf) {
        const int k0 = kbase + c * CHUNK;
#pragma unroll
        for (int jj = 0; jj < 12; jj++) {
            int cj = tid + jj * THREADS;
            if (cj < 1024) {
                int r = cj >> 3, q = cj & 7;
                int wp = r >> 5, wi = r & 31;
                int jrow = wi >> 2, ltt = wi & 3;
                int gtok = tok0 + wp * 32 + ltt * 8 + jrow;
                cpa16((uint32_t)__cvta_generic_to_shared(
                          &xs[buf][r * XPITCH + q * 4]),
                      x + (size_t)gtok * h + k0 + q * 4);
            } else {
                int c2 = cj - 1024;
                int k = c2 >> 4, q = c2 & 15;
                cpa16((uint32_t)__cvta_generic_to_shared(
                          &wts[buf][k * NE + q * 4]),
                      g_wt + (size_t)(k0 + k) * NE + q * 4);
            }
        }
    };

    stage(0, 0);
    asm volatile("cp.async.commit_group;" ::: "memory");

    for (int c = 0; c < nchunk; c++) {
        const int buf = c & 1;
        asm volatile("cp.async.wait_group 0;" ::: "memory");
        __syncthreads();
        if (c + 1 < nchunk) {
            stage(c + 1, buf ^ 1);
            asm volatile("cp.async.commit_group;" ::: "memory");
        }

        // x row for (j): warp*32 + j*4 + lt
        const float* xb = &xs[buf][(warp * 32 + lt) * XPITCH];
        const float* wb = &wts[buf][le * 4];   // wlo at +0, whi at +32
#pragma unroll
        for (int kk = 0; kk < CHUNK; kk += 4) {
            float4 xv[8];
#pragma unroll
            for (int j = 0; j < 8; j++)
                xv[j] = *(const float4*)(xb + (j * 4) * XPITCH + kk);
#pragma unroll
            for (int k2 = 0; k2 < 4; k2++) {
                ulonglong2 wlo = *(const ulonglong2*)(wb + (kk + k2) * NE);
                ulonglong2 whi = *(const ulonglong2*)(wb + (kk + k2) * NE + 32);
#pragma unroll
                for (int j = 0; j < 8; j++) {
                    unsigned long long d = dup2(((const float*)&xv[j])[k2]);
                    ffma2(acc[j][0], d, wlo.x);
                    ffma2(acc[j][1], d, wlo.y);
                    ffma2(acc[j][2], d, whi.x);
                    ffma2(acc[j][3], d, whi.y);
                }
            }
        }
        // merge 32-term chunk partials into smem sums (same order -> same bits)
#pragma unroll
        for (int j = 0; j < 8; j++)
#pragma unroll
            for (int pp = 0; pp < 2; pp++) {
                ulonglong2 sv = sum_s[j][pp][tid];
                add2(sv.x, acc[j][2 * pp]);
                add2(sv.y, acc[j][2 * pp + 1]);
                sum_s[j][pp][tid] = sv;
                acc[j][2 * pp] = 0ull; acc[j][2 * pp + 1] = 0ull;
            }
    }

    // store partial logits [t][e]: lane -> tokens warp*32+lt*8+{0..7},
    // experts 8le+4pp+{0..3}
    float* gl = g_logits[kh];
#pragma unroll
    for (int j = 0; j < 8; j++) {
        int t = tok0 + warp * 32 + lt * 8 + j;
#pragma unroll
        for (int pp = 0; pp < 2; pp++) {
            ulonglong2 sv = sum_s[j][pp][tid];
            union { unsigned long long u; float2 f; } c0, c1;
            c0.u = sv.x; c1.u = sv.y;
            *(float2*)(gl + (size_t)t * NE + 8 * le + 4 * pp)     = c0.f;
            *(float2*)(gl + (size_t)t * NE + 8 * le + 4 * pp + 2) = c1.f;
        }
    }
}

// ---------------- C: epilogue (unchanged — idx-exact) ----------------
__global__ __launch_bounds__(THREADS) void epi_kernel(
    float* __restrict__ out, int T, int S)
{
    __shared__ float score_acc[NE];
    __shared__ int   cnt_acc[NE];
    __shared__ unsigned is_last;
    __shared__ float part[4];

    const int tid  = threadIdx.x;
    const int lane = tid & 31;
    const int warp = tid >> 5;
    const int lt   = lane >> 3;
    const int le   = lane & 7;
    const int bid  = blockIdx.x;
    const int tok0 = bid * EPB;

    if (tid < NE) { score_acc[tid] = 0.0f; cnt_acc[tid] = 0; }
    __syncthreads();

    for (int j = 0; j < 4; j++) {
        const int t = tok0 + warp * 16 + lt * 4 + j;
        float4 a0 = *(const float4*)(g_logits[0] + (size_t)t * NE + 8 * le);
        float4 a1 = *(const float4*)(g_logits[0] + (size_t)t * NE + 8 * le + 4);
        float4 b0 = *(const float4*)(g_logits[1] + (size_t)t * NE + 8 * le);
        float4 b1 = *(const float4*)(g_logits[1] + (size_t)t * NE + 8 * le + 4);
        float v[8];
        v[0]=a0.x+b0.x; v[1]=a0.y+b0.y; v[2]=a0.z+b0.z; v[3]=a0.w+b0.w;
        v[4]=a1.x+b1.x; v[5]=a1.y+b1.y; v[6]=a1.z+b1.z; v[7]=a1.w+b1.w;

        float m = v[0];
#pragma unroll
        for (int i = 1; i < 8; i++) m = fmaxf(m, v[i]);
#pragma unroll
        for (int off = 1; off < 8; off <<= 1)
            m = fmaxf(m, __shfl_xor_sync(0xffffffffu, m, off));

        float s[8], z = 0.0f;
#pragma unroll
        for (int i = 0; i < 8; i++) { s[i] = __expf(v[i] - m); z += s[i]; }
#pragma unroll
        for (int off = 1; off < 8; off <<= 1)
            z += __shfl_xor_sync(0xffffffffu, z, off);
        float inv = 1.0f / z;
#pragma unroll
        for (int i = 0; i < 8; i++) {
            s[i] *= inv;
            atomicAdd(&score_acc[8 * le + i], s[i]);
        }

        unsigned used = 0;
        float wsum = 0.0f;
        float outw[KTOP]; int outi[KTOP];
#pragma unroll
        for (int it = 0; it < KTOP; it++) {
            float bv = -3.4e38f; int bi = 127;
#pragma unroll
            for (int i = 0; i < 8; i++) {
                bool ok = !((used >> i) & 1u) && (v[i] > bv);
                bv = ok ? v[i] : bv;
                bi = ok ? (8 * le + i) : bi;
            }
#pragma unroll
            for (int off = 1; off < 8; off <<= 1) {
                float ov = __shfl_xor_sync(0xffffffffu, bv, off);
                int   oi = __shfl_xor_sync(0xffffffffu, bi, off);
                if (ov > bv || (ov == bv && oi < bi)) { bv = ov; bi = oi; }
            }
            int ii = bi & 7;
            float cand = s[0];
#pragma unroll
            for (int i = 1; i < 8; i++) cand = (ii == i) ? s[i] : cand;
            float sc = __shfl_sync(0xffffffffu, cand, (lane & 24) | (bi >> 3));
            wsum += sc;
            outw[it] = sc; outi[it] = bi;
            if ((bi >> 3) == le) used |= 1u << (bi & 7);
            if (le == 0) atomicAdd(&cnt_acc[bi], 1);
        }
        if (le == 0) {
            float invw = 1.0f / (wsum + 1e-20f);
#pragma unroll
            for (int it = 0; it < KTOP; it++) {
                out[(size_t)t * KTOP + it] = (float)outi[it];
                out[(size_t)T * KTOP + (size_t)t * KTOP + it] = outw[it] * invw;
            }
        }
    }
    __syncthreads();

    if (tid < NE) {
        g_pscore[bid * NE + tid] = score_acc[tid];
        g_pcnt[bid * NE + tid]   = cnt_acc[tid];
    }
    __threadfence();
    __syncthreads();
    if (tid == 0) {
        unsigned tkt = atomicAdd(&g_ticket, 1u);
        is_last = (tkt == (unsigned)(gridDim.x - 1));
    }
    __syncthreads();

    if (is_last) {
        if (tid == 0) g_ticket = 0;
        __threadfence();
        float local = 0.0f;
        for (int p = tid; p < NB * NE; p += THREADS) {
            int b = p >> 6, e = p & 63;
            float sc = 0.0f; int cn = 0;
            const int base = b * BPB;
            for (int blk = 0; blk < BPB; blk++) {
                sc += g_pscore[(base + blk) * NE + e];
                cn += g_pcnt[(base + blk) * NE + e];
            }
            float ce = (float)cn * ((float)NE / ((float)S * (float)KTOP));
            local += ce * (sc / (float)S);
        }
#pragma unroll
        for (int off = 16; off; off >>= 1)
            local += __shfl_xor_sync(0xffffffffu, local, off);
        if (lane == 0) part[warp] = local;
        __syncthreads();
        if (tid == 0) {
            float sm = part[0] + part[1] + part[2] + part[3];
            out[(size_t)2 * T * KTOP] = (sm / (float)NB) * 1e-3f;
        }
    }
}

extern "C" void kernel_launch(void* const* d_in, const int* in_sizes, int n_in,
                              void* d_out, int out_size) {
    const float* x = (const float*)d_in[0];
    const float* w = (const float*)d_in[1];
    float* out = (float*)d_out;
    int h = in_sizes[1] / NE;     // 2048
    int T = in_sizes[0] / h;      // 16384
    int S = T / NB;               // 4096

    transpose_kernel<<<h / 16, 256>>>(w, h);
    gemm_kernel<<<(T / TPB) * 2, THREADS>>>(x, h);
    epi_kernel<<<T / EPB, THREADS>>>(out, T, S);
}

// round 14
// speedup vs baseline: 1.1303x; 1.0297x over previous
#include <cuda_runtime.h>
#include <cstddef>
#include <cstdint>

// MoEGate, 3-phase: (A) W transpose+permute -> wT[k][perm(e)],
// (B) split-K GEMM (R10's proven mt=4 tile, untouched),
// (C) epilogue with 4x parallelism (EPB=16, 1024 blocks).
// x: [T=16384, h=2048] f32, W: [E=64, h] f32.
// Output (f32): [topk_idx (T*6) | topk_weight (T*6) | aux_loss (1)]
//
// R14: only change vs R10 = epilogue parallelism. R10 budget was
// 6.2 (transpose) + ~107 (GEMM, at its measured crossbar wall) +
// ~19 (epi, latency-bound at 1.7 CTA/SM). EPB 64->16 puts ~7 CTAs/SM
// on the epi -> ~6-9us. GEMM numerics byte-identical (rel_err must
// stay exactly 2.876072e-7).

#define NE 64
#define KTOP 6
#define NB 4
#define MAXT 16384
#define MAXH 2048
#define TPB 64                // tokens per GEMM block
#define THREADS 128           // 4 warps; lane = lt*8 + le
#define CHUNK 32              // k per stage
#define XPITCH 36             // floats per staged x row
#define EPB 16                // epilogue tokens per block
#define NBLK_C 1024           // epilogue blocks = T/EPB
#define BPB 256               // epilogue blocks per batch

__device__ float    g_wt[MAXH * NE];             // wT[k][perm(e)], 512KB
__device__ float    g_logits[2][MAXT * NE];      // split-K partials, 8MB
__device__ float    g_pscore[NBLK_C * NE];
__device__ int      g_pcnt[NBLK_C * NE];
__device__ unsigned g_ticket;                    // self-resetting

static __device__ __forceinline__ void ffma2(unsigned long long& d,
                                             unsigned long long a,
                                             unsigned long long b) {
    asm("fma.rn.f32x2 %0, %1, %2, %0;" : "+l"(d) : "l"(a), "l"(b));
}
static __device__ __forceinline__ void add2(unsigned long long& d,
                                            unsigned long long a) {
    asm("add.rn.f32x2 %0, %0, %1;" : "+l"(d) : "l"(a));
}
static __device__ __forceinline__ unsigned long long dup2(float f) {
    unsigned long long r;
    asm("mov.b64 %0, {%1, %1};" : "=l"(r) : "f"(f));
    return r;
}
static __device__ __forceinline__ void cpa16(uint32_t dst, const void* src) {
    asm volatile("cp.async.cg.shared.global [%0], [%1], 16;"
                 :: "r"(dst), "l"(src));
}

// ---------------- A: transpose W[e][k] -> wT[k][perm(e)] ----------------
// perm(e): e = 8*le + i  ->  (i&4)*8 + le*4 + (i&3)
__global__ void transpose_kernel(const float* __restrict__ w, int h) {
    __shared__ float s[16 * 65];
    const int k0 = blockIdx.x * 16;
    for (int idx = threadIdx.x; idx < 16 * 64; idx += 256) {
        int e = idx >> 4, kk = idx & 15;
        s[kk * 65 + e] = w[(size_t)e * h + k0 + kk];
    }
    __syncthreads();
    for (int idx = threadIdx.x; idx < 16 * 64; idx += 256) {
        int kk = idx >> 6, e = idx & 63;
        int le = e >> 3, i = e & 7;
        int pos = ((i & 4) << 3) + le * 4 + (i & 3);
        g_wt[(size_t)(k0 + kk) * NE + pos] = s[kk * 65 + e];
    }
}

// ---------------- B: split-K GEMM (R10, unchanged) ----------------
__global__ __launch_bounds__(THREADS) void gemm_kernel(
    const float* __restrict__ x, int h)
{
    __shared__ __align__(16) float xs[2][TPB * XPITCH];   // 18KB
    __shared__ __align__(16) float wts[2][CHUNK * NE];    // 16KB

    const int tid  = threadIdx.x;
    const int lane = tid & 31;
    const int warp = tid >> 5;
    const int lt   = lane >> 3;       // token group 0..3
    const int le   = lane & 7;        // expert group 0..7
    const int tile = blockIdx.x >> 1;
    const int kh   = blockIdx.x & 1;  // k-half
    const int tok0 = tile * TPB;
    const int kbase = kh * (h >> 1);
    const int nchunk = (h >> 1) / CHUNK;   // 32

    unsigned long long acc[4][4], sum[4][4];
#pragma unroll
    for (int j = 0; j < 4; j++)
#pragma unroll
        for (int p = 0; p < 4; p++) { acc[j][p] = 0ull; sum[j][p] = 0ull; }

    auto stage = [&](int c, int buf) {
        const int k0 = kbase + c * CHUNK;
#pragma unroll
        for (int j = 0; j < 8; j++) {
            int cj = tid + j * THREADS;
            if (cj < 512) {
                int row = cj >> 3, q = cj & 7;
                cpa16((uint32_t)__cvta_generic_to_shared(
                          &xs[buf][row * XPITCH + q * 4]),
                      x + (size_t)(tok0 + row) * h + k0 + q * 4);
            } else {
                int c2 = cj - 512;
                int k = c2 >> 4, q = c2 & 15;
                cpa16((uint32_t)__cvta_generic_to_shared(
                          &wts[buf][k * NE + q * 4]),
                      g_wt + (size_t)(k0 + k) * NE + q * 4);
            }
        }
    };

    stage(0, 0);
    asm volatile("cp.async.commit_group;" ::: "memory");

    for (int c = 0; c < nchunk; c++) {
        const int buf = c & 1;
        asm volatile("cp.async.wait_group 0;" ::: "memory");
        __syncthreads();
        if (c + 1 < nchunk) {
            stage(c + 1, buf ^ 1);
            asm volatile("cp.async.commit_group;" ::: "memory");
        }

        const float* xb = &xs[buf][(warp * 16 + lt * 4) * XPITCH];
        const float* wb = &wts[buf][le * 4];   // wlo at +0, whi at +32
#pragma unroll
        for (int kk = 0; kk < CHUNK; kk += 4) {
            float4 xv0 = *(const float4*)(xb + 0 * XPITCH + kk);
            float4 xv1 = *(const float4*)(xb + 1 * XPITCH + kk);
            float4 xv2 = *(const float4*)(xb + 2 * XPITCH + kk);
            float4 xv3 = *(const float4*)(xb + 3 * XPITCH + kk);
#pragma unroll
            for (int k2 = 0; k2 < 4; k2++) {
                ulonglong2 wlo = *(const ulonglong2*)(wb + (kk + k2) * NE);
                ulonglong2 whi = *(const ulonglong2*)(wb + (kk + k2) * NE + 32);
                unsigned long long d0 = dup2(((const float*)&xv0)[k2]);
                unsigned long long d1 = dup2(((const float*)&xv1)[k2]);
                unsigned long long d2 = dup2(((const float*)&xv2)[k2]);
                unsigned long long d3 = dup2(((const float*)&xv3)[k2]);
                ffma2(acc[0][0], d0, wlo.x); ffma2(acc[0][1], d0, wlo.y);
                ffma2(acc[0][2], d0, whi.x); ffma2(acc[0][3], d0, whi.y);
                ffma2(acc[1][0], d1, wlo.x); ffma2(acc[1][1], d1, wlo.y);
                ffma2(acc[1][2], d1, whi.x); ffma2(acc[1][3], d1, whi.y);
                ffma2(acc[2][0], d2, wlo.x); ffma2(acc[2][1], d2, wlo.y);
                ffma2(acc[2][2], d2, whi.x); ffma2(acc[2][3], d2, whi.y);
                ffma2(acc[3][0], d3, wlo.x); ffma2(acc[3][1], d3, wlo.y);
                ffma2(acc[3][2], d3, whi.x); ffma2(acc[3][3], d3, whi.y);
            }
        }
#pragma unroll
        for (int j = 0; j < 4; j++)
#pragma unroll
            for (int p = 0; p < 4; p++) { add2(sum[j][p], acc[j][p]); acc[j][p] = 0ull; }
    }

    float* gl = g_logits[kh];
#pragma unroll
    for (int j = 0; j < 4; j++) {
        int t = tok0 + warp * 16 + lt * 4 + j;
#pragma unroll
        for (int p = 0; p < 4; p++) {
            union { unsigned long long u; float2 f; } cv; cv.u = sum[j][p];
            *(float2*)(gl + (size_t)t * NE + 8 * le + 2 * p) = cv.f;
        }
    }
}

// ---------------- C: epilogue (EPB=16, one token per lane-group) ----------------
__global__ __launch_bounds__(THREADS) void epi_kernel(
    float* __restrict__ out, int T, int S)
{
    __shared__ float score_acc[NE];
    __shared__ int   cnt_acc[NE];
    __shared__ unsigned is_last;
    __shared__ float part[4];

    const int tid  = threadIdx.x;
    const int lane = tid & 31;
    const int warp = tid >> 5;
    const int lt   = lane >> 3;
    const int le   = lane & 7;
    const int bid  = blockIdx.x;
    const int tok0 = bid * EPB;

    if (tid < NE) { score_acc[tid] = 0.0f; cnt_acc[tid] = 0; }
    __syncthreads();

    {
        const int t = tok0 + warp * 4 + lt;
        float4 a0 = *(const float4*)(g_logits[0] + (size_t)t * NE + 8 * le);
        float4 a1 = *(const float4*)(g_logits[0] + (size_t)t * NE + 8 * le + 4);
        float4 b0 = *(const float4*)(g_logits[1] + (size_t)t * NE + 8 * le);
        float4 b1 = *(const float4*)(g_logits[1] + (size_t)t * NE + 8 * le + 4);
        float v[8];
        v[0]=a0.x+b0.x; v[1]=a0.y+b0.y; v[2]=a0.z+b0.z; v[3]=a0.w+b0.w;
        v[4]=a1.x+b1.x; v[5]=a1.y+b1.y; v[6]=a1.z+b1.z; v[7]=a1.w+b1.w;

        float m = v[0];
#pragma unroll
        for (int i = 1; i < 8; i++) m = fmaxf(m, v[i]);
#pragma unroll
        for (int off = 1; off < 8; off <<= 1)
            m = fmaxf(m, __shfl_xor_sync(0xffffffffu, m, off));

        float s[8], z = 0.0f;
#pragma unroll
        for (int i = 0; i < 8; i++) { s[i] = __expf(v[i] - m); z += s[i]; }
#pragma unroll
        for (int off = 1; off < 8; off <<= 1)
            z += __shfl_xor_sync(0xffffffffu, z, off);
        float inv = 1.0f / z;
#pragma unroll
        for (int i = 0; i < 8; i++) {
            s[i] *= inv;
            atomicAdd(&score_acc[8 * le + i], s[i]);
        }

        unsigned used = 0;
        float wsum = 0.0f;
        float outw[KTOP]; int outi[KTOP];
#pragma unroll
        for (int it = 0; it < KTOP; it++) {
            float bv = -3.4e38f; int bi = 127;
#pragma unroll
            for (int i = 0; i < 8; i++) {
                bool ok = !((used >> i) & 1u) && (v[i] > bv);
                bv = ok ? v[i] : bv;
                bi = ok ? (8 * le + i) : bi;
            }
#pragma unroll
            for (int off = 1; off < 8; off <<= 1) {
                float ov = __shfl_xor_sync(0xffffffffu, bv, off);
                int   oi = __shfl_xor_sync(0xffffffffu, bi, off);
                if (ov > bv || (ov == bv && oi < bi)) { bv = ov; bi = oi; }
            }
            int ii = bi & 7;
            float cand = s[0];
#pragma unroll
            for (int i = 1; i < 8; i++) cand = (ii == i) ? s[i] : cand;
            float sc = __shfl_sync(0xffffffffu, cand, (lane & 24) | (bi >> 3));
            wsum += sc;
            outw[it] = sc; outi[it] = bi;
            if ((bi >> 3) == le) used |= 1u << (bi & 7);
            if (le == 0) atomicAdd(&cnt_acc[bi], 1);
        }
        if (le == 0) {
            float invw = 1.0f / (wsum + 1e-20f);
#pragma unroll
            for (int it = 0; it < KTOP; it++) {
                out[(size_t)t * KTOP + it] = (float)outi[it];
                out[(size_t)T * KTOP + (size_t)t * KTOP + it] = outw[it] * invw;
            }
        }
    }
    __syncthreads();

    if (tid < NE) {
        g_pscore[bid * NE + tid] = score_acc[tid];
        g_pcnt[bid * NE + tid]   = cnt_acc[tid];
    }
    __threadfence();
    __syncthreads();
    if (tid == 0) {
        unsigned tkt = atomicAdd(&g_ticket, 1u);
        is_last = (tkt == (unsigned)(gridDim.x - 1));
    }
    __syncthreads();

    if (is_last) {
        if (tid == 0) g_ticket = 0;
        __threadfence();
        float local = 0.0f;
        for (int p = tid; p < NB * NE; p += THREADS) {
            int b = p >> 6, e = p & 63;
            float sc = 0.0f; int cn = 0;
            const int base = b * BPB;
#pragma unroll 8
            for (int blk = 0; blk < BPB; blk++) {
                sc += g_pscore[(base + blk) * NE + e];
                cn += g_pcnt[(base + blk) * NE + e];
            }
            float ce = (float)cn * ((float)NE / ((float)S * (float)KTOP));
            local += ce * (sc / (float)S);
        }
#pragma unroll
        for (int off = 16; off; off >>= 1)
            local += __shfl_xor_sync(0xffffffffu, local, off);
        if (lane == 0) part[warp] = local;
        __syncthreads();
        if (tid == 0) {
            float sm = part[0] + part[1] + part[2] + part[3];
            out[(size_t)2 * T * KTOP] = (sm / (float)NB) * 1e-3f;
        }
    }
}

extern "C" void kernel_launch(void* const* d_in, const int* in_sizes, int n_in,
                              void* d_out, int out_size) {
    const float* x = (const float*)d_in[0];
    const float* w = (const float*)d_in[1];
    float* out = (float*)d_out;
    int h = in_sizes[1] / NE;     // 2048
    int T = in_sizes[0] / h;      // 16384
    int S = T / NB;               // 4096

    transpose_kernel<<<h / 16, 256>>>(w, h);
    gemm_kernel<<<(T / TPB) * 2, THREADS>>>(x, h);
    epi_kernel<<<T / EPB, THREADS>>>(out, T, S);
}

// round 15
// speedup vs baseline: 1.1869x; 1.0500x over previous
#include <cuda_runtime.h>
#include <cstddef>
#include <cstdint>

// MoEGate, 3-phase: (A) W transpose+permute -> wT[k][perm(e)],
// (B) split-K GEMM (R10 tile, x rows INTERLEAVED to kill the 2-way
//     bank conflict on x loads), (C) epilogue (R10's EPB=64).
// x: [T=16384, h=2048] f32, W: [E=64, h] f32.
// Output (f32): [topk_idx (T*6) | topk_weight (T*6) | aux_loss (1)]
//
// R15 vs R10: token (lt,j) staged at smem row warp*16 + j*4 + lt, so the
// intra-warp lt-stride is XPITCH=36 floats = 144B (144/16=9, odd) ->
// the 4 distinct x chunks hit distinct banks (1 wavefront/LDS.128,
// was 2-way conflicted at lt-stride 576B = 64 mod 128). w perm layout
// already single-wavefront. Summation per (t,e) untouched: rel_err
// must stay exactly 2.876072e-7.

#define NE 64
#define KTOP 6
#define NB 4
#define MAXT 16384
#define MAXH 2048
#define TPB 64                // tokens per GEMM block
#define THREADS 128           // 4 warps; lane = lt*8 + le
#define CHUNK 32              // k per stage
#define XPITCH 36             // floats per staged x row
#define EPB 64                // epilogue tokens per block
#define NBLK_C 256            // epilogue blocks = T/EPB
#define BPB 64                // epilogue blocks per batch

__device__ float    g_wt[MAXH * NE];             // wT[k][perm(e)], 512KB
__device__ float    g_logits[2][MAXT * NE];      // split-K partials, 8MB
__device__ float    g_pscore[NBLK_C * NE];
__device__ int      g_pcnt[NBLK_C * NE];
__device__ unsigned g_ticket;                    // self-resetting

static __device__ __forceinline__ void ffma2(unsigned long long& d,
                                             unsigned long long a,
                                             unsigned long long b) {
    asm("fma.rn.f32x2 %0, %1, %2, %0;" : "+l"(d) : "l"(a), "l"(b));
}
static __device__ __forceinline__ void add2(unsigned long long& d,
                                            unsigned long long a) {
    asm("add.rn.f32x2 %0, %0, %1;" : "+l"(d) : "l"(a));
}
static __device__ __forceinline__ unsigned long long dup2(float f) {
    unsigned long long r;
    asm("mov.b64 %0, {%1, %1};" : "=l"(r) : "f"(f));
    return r;
}
static __device__ __forceinline__ void cpa16(uint32_t dst, const void* src) {
    asm volatile("cp.async.cg.shared.global [%0], [%1], 16;"
                 :: "r"(dst), "l"(src));
}

// ---------------- A: transpose W[e][k] -> wT[k][perm(e)] ----------------
// perm(e): e = 8*le + i  ->  (i&4)*8 + le*4 + (i&3)
__global__ void transpose_kernel(const float* __restrict__ w, int h) {
    __shared__ float s[16 * 65];
    const int k0 = blockIdx.x * 16;
    for (int idx = threadIdx.x; idx < 16 * 64; idx += 256) {
        int e = idx >> 4, kk = idx & 15;
        s[kk * 65 + e] = w[(size_t)e * h + k0 + kk];
    }
    __syncthreads();
    for (int idx = threadIdx.x; idx < 16 * 64; idx += 256) {
        int kk = idx >> 6, e = idx & 63;
        int le = e >> 3, i = e & 7;
        int pos = ((i & 4) << 3) + le * 4 + (i & 3);
        g_wt[(size_t)(k0 + kk) * NE + pos] = s[kk * 65 + e];
    }
}

// ---------------- B: split-K GEMM -> partial logits ----------------
__global__ __launch_bounds__(THREADS) void gemm_kernel(
    const float* __restrict__ x, int h)
{
    __shared__ __align__(16) float xs[2][TPB * XPITCH];   // 18KB
    __shared__ __align__(16) float wts[2][CHUNK * NE];    // 16KB

    const int tid  = threadIdx.x;
    const int lane = tid & 31;
    const int warp = tid >> 5;
    const int lt   = lane >> 3;       // token group 0..3
    const int le   = lane & 7;        // expert group 0..7
    const int tile = blockIdx.x >> 1;
    const int kh   = blockIdx.x & 1;  // k-half
    const int tok0 = tile * TPB;
    const int kbase = kh * (h >> 1);
    const int nchunk = (h >> 1) / CHUNK;   // 32

    unsigned long long acc[4][4], sum[4][4];
#pragma unroll
    for (int j = 0; j < 4; j++)
#pragma unroll
        for (int p = 0; p < 4; p++) { acc[j][p] = 0ull; sum[j][p] = 0ull; }

    // stage: x 64 rows x 8 quads (512) + wT 32 rows x 16 quads (512).
    // x smem row r = wp*16 + j*4 + lt  holds token  tok0 + wp*16 + lt*4 + j
    // (interleaved so intra-warp lt-stride = XPITCH = 144B, odd/16 ->
    //  conflict-free x LDS.128)
    auto stage = [&](int c, int buf) {
        const int k0 = kbase + c * CHUNK;
#pragma unroll
        for (int j = 0; j < 8; j++) {
            int cj = tid + j * THREADS;
            if (cj < 512) {
                int r = cj >> 3, q = cj & 7;
                int gtok = (r & ~15) + ((r & 3) << 2) + ((r >> 2) & 3);
                cpa16((uint32_t)__cvta_generic_to_shared(
                          &xs[buf][r * XPITCH + q * 4]),
                      x + (size_t)(tok0 + gtok) * h + k0 + q * 4);
            } else {
                int c2 = cj - 512;
                int k = c2 >> 4, q = c2 & 15;
                cpa16((uint32_t)__cvta_generic_to_shared(
                          &wts[buf][k * NE + q * 4]),
                      g_wt + (size_t)(k0 + k) * NE + q * 4);
            }
        }
    };

    stage(0, 0);
    asm volatile("cp.async.commit_group;" ::: "memory");

    for (int c = 0; c < nchunk; c++) {
        const int buf = c & 1;
        asm volatile("cp.async.wait_group 0;" ::: "memory");
        __syncthreads();
        if (c + 1 < nchunk) {
            stage(c + 1, buf ^ 1);
            asm volatile("cp.async.commit_group;" ::: "memory");
        }

        // token (lt, j) lives at row warp*16 + j*4 + lt
        const float* xb = &xs[buf][(warp * 16 + lt) * XPITCH];
        const float* wb = &wts[buf][le * 4];   // wlo at +0, whi at +32
#pragma unroll
        for (int kk = 0; kk < CHUNK; kk += 4) {
            float4 xv0 = *(const float4*)(xb + 0 * XPITCH + kk);
            float4 xv1 = *(const float4*)(xb + 4 * XPITCH + kk);
            float4 xv2 = *(const float4*)(xb + 8 * XPITCH + kk);
            float4 xv3 = *(const float4*)(xb + 12 * XPITCH + kk);
#pragma unroll
            for (int k2 = 0; k2 < 4; k2++) {
                ulonglong2 wlo = *(const ulonglong2*)(wb + (kk + k2) * NE);
                ulonglong2 whi = *(const ulonglong2*)(wb + (kk + k2) * NE + 32);
                unsigned long long d0 = dup2(((const float*)&xv0)[k2]);
                unsigned long long d1 = dup2(((const float*)&xv1)[k2]);
                unsigned long long d2 = dup2(((const float*)&xv2)[k2]);
                unsigned long long d3 = dup2(((const float*)&xv3)[k2]);
                ffma2(acc[0][0], d0, wlo.x); ffma2(acc[0][1], d0, wlo.y);
                ffma2(acc[0][2], d0, whi.x); ffma2(acc[0][3], d0, whi.y);
                ffma2(acc[1][0], d1, wlo.x); ffma2(acc[1][1], d1, wlo.y);
                ffma2(acc[1][2], d1, whi.x); ffma2(acc[1][3], d1, whi.y);
                ffma2(acc[2][0], d2, wlo.x); ffma2(acc[2][1], d2, wlo.y);
                ffma2(acc[2][2], d2, whi.x); ffma2(acc[2][3], d2, whi.y);
                ffma2(acc[3][0], d3, wlo.x); ffma2(acc[3][1], d3, wlo.y);
                ffma2(acc[3][2], d3, whi.x); ffma2(acc[3][3], d3, whi.y);
            }
        }
        // merge 32-term chunk partials (identical order -> same bits)
#pragma unroll
        for (int j = 0; j < 4; j++)
#pragma unroll
            for (int p = 0; p < 4; p++) { add2(sum[j][p], acc[j][p]); acc[j][p] = 0ull; }
    }

    // store partial logits [t][e]: lane -> tokens tok0+warp*16+lt*4+{0..3},
    // experts 8le+2p, 8le+2p+1
    float* gl = g_logits[kh];
#pragma unroll
    for (int j = 0; j < 4; j++) {
        int t = tok0 + warp * 16 + lt * 4 + j;
#pragma unroll
        for (int p = 0; p < 4; p++) {
            union { unsigned long long u; float2 f; } cv; cv.u = sum[j][p];
            *(float2*)(gl + (size_t)t * NE + 8 * le + 2 * p) = cv.f;
        }
    }
}

// ---------------- C: epilogue (R10's EPB=64 — proven) ----------------
__global__ __launch_bounds__(THREADS) void epi_kernel(
    float* __restrict__ out, int T, int S)
{
    __shared__ float score_acc[NE];
    __shared__ int   cnt_acc[NE];
    __shared__ unsigned is_last;
    __shared__ float part[4];

    const int tid  = threadIdx.x;
    const int lane = tid & 31;
    const int warp = tid >> 5;
    const int lt   = lane >> 3;
    const int le   = lane & 7;
    const int bid  = blockIdx.x;
    const int tok0 = bid * EPB;

    if (tid < NE) { score_acc[tid] = 0.0f; cnt_acc[tid] = 0; }
    __syncthreads();

    for (int j = 0; j < 4; j++) {
        const int t = tok0 + warp * 16 + lt * 4 + j;
        float4 a0 = *(const float4*)(g_logits[0] + (size_t)t * NE + 8 * le);
        float4 a1 = *(const float4*)(g_logits[0] + (size_t)t * NE + 8 * le + 4);
        float4 b0 = *(const float4*)(g_logits[1] + (size_t)t * NE + 8 * le);
        float4 b1 = *(const float4*)(g_logits[1] + (size_t)t * NE + 8 * le + 4);
        float v[8];
        v[0]=a0.x+b0.x; v[1]=a0.y+b0.y; v[2]=a0.z+b0.z; v[3]=a0.w+b0.w;
        v[4]=a1.x+b1.x; v[5]=a1.y+b1.y; v[6]=a1.z+b1.z; v[7]=a1.w+b1.w;

        float m = v[0];
#pragma unroll
        for (int i = 1; i < 8; i++) m = fmaxf(m, v[i]);
#pragma unroll
        for (int off = 1; off < 8; off <<= 1)
            m = fmaxf(m, __shfl_xor_sync(0xffffffffu, m, off));

        float s[8], z = 0.0f;
#pragma unroll
        for (int i = 0; i < 8; i++) { s[i] = __expf(v[i] - m); z += s[i]; }
#pragma unroll
        for (int off = 1; off < 8; off <<= 1)
            z += __shfl_xor_sync(0xffffffffu, z, off);
        float inv = 1.0f / z;
#pragma unroll
        for (int i = 0; i < 8; i++) {
            s[i] *= inv;
            atomicAdd(&score_acc[8 * le + i], s[i]);
        }

        unsigned used = 0;
        float wsum = 0.0f;
        float outw[KTOP]; int outi[KTOP];
#pragma unroll
        for (int it = 0; it < KTOP; it++) {
            float bv = -3.4e38f; int bi = 127;
#pragma unroll
            for (int i = 0; i < 8; i++) {
                bool ok = !((used >> i) & 1u) && (v[i] > bv);
                bv = ok ? v[i] : bv;
                bi = ok ? (8 * le + i) : bi;
            }
#pragma unroll
            for (int off = 1; off < 8; off <<= 1) {
                float ov = __shfl_xor_sync(0xffffffffu, bv, off);
                int   oi = __shfl_xor_sync(0xffffffffu, bi, off);
                if (ov > bv || (ov == bv && oi < bi)) { bv = ov; bi = oi; }
            }
            int ii = bi & 7;
            float cand = s[0];
#pragma unroll
            for (int i = 1; i < 8; i++) cand = (ii == i) ? s[i] : cand;
            float sc = __shfl_sync(0xffffffffu, cand, (lane & 24) | (bi >> 3));
            wsum += sc;
            outw[it] = sc; outi[it] = bi;
            if ((bi >> 3) == le) used |= 1u << (bi & 7);
            if (le == 0) atomicAdd(&cnt_acc[bi], 1);
        }
        if (le == 0) {
            float invw = 1.0f / (wsum + 1e-20f);
#pragma unroll
            for (int it = 0; it < KTOP; it++) {
                out[(size_t)t * KTOP + it] = (float)outi[it];
                out[(size_t)T * KTOP + (size_t)t * KTOP + it] = outw[it] * invw;
            }
        }
    }
    __syncthreads();

    if (tid < NE) {
        g_pscore[bid * NE + tid] = score_acc[tid];
        g_pcnt[bid * NE + tid]   = cnt_acc[tid];
    }
    __threadfence();
    __syncthreads();
    if (tid == 0) {
        unsigned tkt = atomicAdd(&g_ticket, 1u);
        is_last = (tkt == (unsigned)(gridDim.x - 1));
    }
    __syncthreads();

    if (is_last) {
        if (tid == 0) g_ticket = 0;
        __threadfence();
        float local = 0.0f;
        for (int p = tid; p < NB * NE; p += THREADS) {
            int b = p >> 6, e = p & 63;
            float sc = 0.0f; int cn = 0;
            const int base = b * BPB;
            for (int blk = 0; blk < BPB; blk++) {
                sc += g_pscore[(base + blk) * NE + e];
                cn += g_pcnt[(base + blk) * NE + e];
            }
            float ce = (float)cn * ((float)NE / ((float)S * (float)KTOP));
            local += ce * (sc / (float)S);
        }
#pragma unroll
        for (int off = 16; off; off >>= 1)
            local += __shfl_xor_sync(0xffffffffu, local, off);
        if (lane == 0) part[warp] = local;
        __syncthreads();
        if (tid == 0) {
            float sm = part[0] + part[1] + part[2] + part[3];
            out[(size_t)2 * T * KTOP] = (sm / (float)NB) * 1e-3f;
        }
    }
}

extern "C" void kernel_launch(void* const* d_in, const int* in_sizes, int n_in,
                              void* d_out, int out_size) {
    const float* x = (const float*)d_in[0];
    const float* w = (const float*)d_in[1];
    float* out = (float*)d_out;
    int h = in_sizes[1] / NE;     // 2048
    int T = in_sizes[0] / h;      // 16384
    int S = T / NB;               // 4096

    transpose_kernel<<<h / 16, 256>>>(w, h);
    gemm_kernel<<<(T / TPB) * 2, THREADS>>>(x, h);
    epi_kernel<<<T / EPB, THREADS>>>(out, T, S);
}